// round 1
// baseline (speedup 1.0000x reference)
#include <cuda_runtime.h>
#include <math.h>

// Problem constants
#define BB 8192
#define NN 8
#define HH 256
#define HHALF 128
#define P3 24          // 3*N nodes per sample
#define E_PER 90
#define EDGE_DIM 16

// Output layout (float32 concat of the 4 reference outputs)
#define OFF_NODE 0
#define NODE_ELEMS 50331648      // B*24*256
#define OFF_EI 50331648
#define EI_HALF 737280           // B*90
#define OFF_EA 51806208          // OFF_EI + 2*EI_HALF
#define OFF_BV 63602688          // OFF_EA + B*90*16

// ---------------------------------------------------------------------------
// aux kernel: node_feats copy, edge_index, temporal edge_attr, batch_vec
// ---------------------------------------------------------------------------
__global__ void __launch_bounds__(256)
aux_kernel(const float4* __restrict__ text, const float4* __restrict__ audio,
           const float4* __restrict__ facial, const float* __restrict__ emb,
           float* __restrict__ out)
{
    const int b = blockIdx.x;
    const int t = threadIdx.x;

    // ---- node_feats copy: 1536 float4 per sample ----
    float4* out4 = (float4*)(out + OFF_NODE);
#pragma unroll
    for (int u = 0; u < 6; ++u) {
        int idx = u * 256 + t;           // 0..1535
        int j = idx >> 6;                // node 0..23
        int c = idx & 63;                // float4 col
        const float4* s = (j < 8) ? text : ((j < 16) ? audio : facial);
        out4[b * 1536 + idx] = s[(b * 8 + (j & 7)) * 64 + c];
    }

    // ---- edge_index ----
    if (t < E_PER) {
        int src, dst;
        if (t < 42) {
            int m = t / 14, r = t % 14, i = r >> 1, d = r & 1;
            int u_ = m * 8 + i, v_ = u_ + 1;
            src = d ? v_ : u_;
            dst = d ? u_ : v_;
        } else {
            int e2 = t - 42;
            int P = e2 >> 4, r = e2 & 15, i = r >> 1, d = r & 1;
            int oa = (P == 2) ? 8 : 0;
            int ob = (P == 0) ? 8 : 16;
            int a_ = oa + i, b_ = ob + i;
            src = d ? b_ : a_;
            dst = d ? a_ : b_;
        }
        out[OFF_EI + b * E_PER + t]           = (float)(src + b * P3);
        out[OFF_EI + EI_HALF + b * E_PER + t] = (float)(dst + b * P3);
    }

    // ---- temporal edge_attr: first 42 edges, 16 floats each = 672 ----
    for (int o = t; o < 672; o += 256) {
        int e = o >> 4, j = o & 15;
        int m = e / 14;
        float v;
        if (j < 8)       v = emb[m * 8 + j];
        else if (j == 9)  v = 0.125f;          // 1/N
        else if (j == 10) v = 1.0f;            // direction
        else if (j == 11) v = m * 0.25f;       // etype/4
        else              v = 0.0f;
        out[OFF_EA + (b * E_PER + e) * EDGE_DIM + j] = v;
    }

    // ---- batch_vec ----
    if (t < P3) out[OFF_BV + b * P3 + t] = (float)b;
}

// ---------------------------------------------------------------------------
// projection kernel: per-sample q/k projections + l2norm dots + cross attrs
// smem: Wt (256x132 f32 = 132KB, W transposed, padded) | ns (16x256) |
//       partial (8x16x128) | qbuf (16x128).  kbuf aliases Wt start.
// ---------------------------------------------------------------------------
#define SM_WT 0
#define SM_NS 33792
#define SM_PART 37888
#define SM_QBUF 54272
#define SM_TOTAL_FLOATS 56320    // 225280 bytes

__global__ void __launch_bounds__(256, 1)
proj_kernel(const float4* __restrict__ text, const float4* __restrict__ audio,
            const float4* __restrict__ facial,
            const float4* __restrict__ Wq4, const float* __restrict__ bq,
            const float4* __restrict__ Wk4, const float* __restrict__ bk,
            const float* __restrict__ emb, float* __restrict__ out)
{
    extern __shared__ float sm[];
    float* Wt      = sm + SM_WT;     // 33792 floats (stride 132 per k-row)
    float* ns      = sm + SM_NS;     // 4096
    float* partial = sm + SM_PART;   // 16384
    float* qbuf    = sm + SM_QBUF;   // 2048
    float* kbuf    = sm + SM_WT;     // alias (Wt dead by then)
    float* disc_s  = sm + SM_PART;   // alias (partial dead by then)

    const int b = blockIdx.x;
    const int t = threadIdx.x;
    const int l = t & 31;
    const int w = t >> 5;

    float4* ns4 = (float4*)ns;
    const float4* Wt4 = (const float4*)Wt;

    for (int ph = 0; ph < 2; ++ph) {
        __syncthreads();
        // load 16 node rows: phase0 -> nodes 0..15 (q), phase1 -> nodes 8..23 (k)
#pragma unroll
        for (int it = 0; it < 4; ++it) {
            int idx = it * 256 + t;          // 0..1023 float4
            int c = idx >> 6, k4 = idx & 63;
            int node = ph ? (c + 8) : c;
            const float4* s = (node < 8) ? text : ((node < 16) ? audio : facial);
            ns4[idx] = s[(b * 8 + (node & 7)) * 64 + k4];
        }
        // load W transposed into Wt: Wt[k*132 + d] = W[d][k]
        const float4* Wg = ph ? Wk4 : Wq4;
        for (int it = 0; it < 32; ++it) {
            int idx = it * 256 + t;          // 0..8191 float4 of W
            int d = idx >> 6, k4 = idx & 63;
            float4 v = Wg[idx];
            Wt[(4 * k4 + 0) * 132 + d] = v.x;
            Wt[(4 * k4 + 1) * 132 + d] = v.y;
            Wt[(4 * k4 + 2) * 132 + d] = v.z;
            Wt[(4 * k4 + 3) * 132 + d] = v.w;
        }
        __syncthreads();

        // compute: warp w owns k in [32w, 32w+32); lane l owns dims 4l..4l+3
        float4 acc[16];
#pragma unroll
        for (int c = 0; c < 16; ++c) acc[c] = make_float4(0.f, 0.f, 0.f, 0.f);

        const int kbase = w * 32;
#pragma unroll 1
        for (int kk = 0; kk < 32; kk += 4) {
            int k = kbase + kk;
            float4 w0 = Wt4[(k + 0) * 33 + l];
            float4 w1 = Wt4[(k + 1) * 33 + l];
            float4 w2 = Wt4[(k + 2) * 33 + l];
            float4 w3 = Wt4[(k + 3) * 33 + l];
#pragma unroll
            for (int c = 0; c < 16; ++c) {
                float4 nv = ns4[c * 64 + (k >> 2)];
                acc[c].x = fmaf(w0.x, nv.x, acc[c].x);
                acc[c].y = fmaf(w0.y, nv.x, acc[c].y);
                acc[c].z = fmaf(w0.z, nv.x, acc[c].z);
                acc[c].w = fmaf(w0.w, nv.x, acc[c].w);
                acc[c].x = fmaf(w1.x, nv.y, acc[c].x);
                acc[c].y = fmaf(w1.y, nv.y, acc[c].y);
                acc[c].z = fmaf(w1.z, nv.y, acc[c].z);
                acc[c].w = fmaf(w1.w, nv.y, acc[c].w);
                acc[c].x = fmaf(w2.x, nv.z, acc[c].x);
                acc[c].y = fmaf(w2.y, nv.z, acc[c].y);
                acc[c].z = fmaf(w2.z, nv.z, acc[c].z);
                acc[c].w = fmaf(w2.w, nv.z, acc[c].w);
                acc[c].x = fmaf(w3.x, nv.w, acc[c].x);
                acc[c].y = fmaf(w3.y, nv.w, acc[c].y);
                acc[c].z = fmaf(w3.z, nv.w, acc[c].z);
                acc[c].w = fmaf(w3.w, nv.w, acc[c].w);
            }
        }
        // store partials: partial[(w*16+c)*128 + 4l .. +3]
#pragma unroll
        for (int c = 0; c < 16; ++c)
            ((float4*)partial)[(w * 16 + c) * 32 + l] = acc[c];
        __syncthreads();

        // reduce over 8 warps + bias
        const float* bias = ph ? bk : bq;
        float* obuf = ph ? kbuf : qbuf;
        for (int o = t; o < 2048; o += 256) {
            int d = o & 127;
            float s = bias[d];
#pragma unroll
            for (int ww = 0; ww < 8; ++ww) s += partial[ww * 2048 + o];
            obuf[o] = s;
        }
    }
    __syncthreads();

    // pair dots: 24 pairs, 3 per warp
#pragma unroll
    for (int s = 0; s < 3; ++s) {
        int p = w * 3 + s;              // 0..23
        int P = p >> 3, i = p & 7;
        int ca = (P < 2) ? i : (8 + i);        // q row (node index, 0..15)
        int cb = (P == 0) ? i : (8 + i);       // k row (node-8, 0..15)
        float4 q  = ((const float4*)qbuf)[ca * 32 + l];
        float4 kv = ((const float4*)kbuf)[cb * 32 + l];
        float sqk = q.x * kv.x + q.y * kv.y + q.z * kv.z + q.w * kv.w;
        float sqq = q.x * q.x + q.y * q.y + q.z * q.z + q.w * q.w;
        float skk = kv.x * kv.x + kv.y * kv.y + kv.z * kv.z + kv.w * kv.w;
#pragma unroll
        for (int off = 16; off > 0; off >>= 1) {
            sqk += __shfl_xor_sync(0xffffffffu, sqk, off);
            sqq += __shfl_xor_sync(0xffffffffu, sqq, off);
            skk += __shfl_xor_sync(0xffffffffu, skk, off);
        }
        if (l == 0) {
            float qn = fmaxf(sqrtf(sqq), 1e-12f);
            float kn = fmaxf(sqrtf(skk), 1e-12f);
            float dv = sqk / (qn * kn);
            float disc = 1.0f - 1.0f / (1.0f + expf(-dv));
            disc_s[p] = disc;
        }
    }
    __syncthreads();

    // cross edge attrs: 24 pairs * 2 dirs * 16 floats = 768 (contiguous)
    for (int o = t; o < 768; o += 256) {
        int p = o >> 5, r = o & 31;
        int e = 42 + 2 * p + (r >> 4);
        int j = r & 15;
        float disc = disc_s[p];
        int et = (disc > 0.4f) ? 4 : 3;
        float v;
        if (j < 8)        v = emb[et * 8 + j];
        else if (j == 8)  v = disc;
        else if (j == 11) v = et * 0.25f;
        else              v = 0.0f;
        out[OFF_EA + (b * E_PER + e) * EDGE_DIM + j] = v;
    }
}

// ---------------------------------------------------------------------------
extern "C" void kernel_launch(void* const* d_in, const int* in_sizes, int n_in,
                              void* d_out, int out_size)
{
    const float* z_text   = (const float*)d_in[0];
    const float* z_audio  = (const float*)d_in[1];
    const float* z_facial = (const float*)d_in[2];
    const float* Wq       = (const float*)d_in[3];
    const float* bq       = (const float*)d_in[4];
    const float* Wk       = (const float*)d_in[5];
    const float* bk       = (const float*)d_in[6];
    const float* emb      = (const float*)d_in[7];
    float* out = (float*)d_out;

    static_assert(SM_TOTAL_FLOATS * 4 == 225280, "smem layout");
    cudaFuncSetAttribute(proj_kernel, cudaFuncAttributeMaxDynamicSharedMemorySize,
                         SM_TOTAL_FLOATS * 4);

    aux_kernel<<<BB, 256>>>((const float4*)z_text, (const float4*)z_audio,
                            (const float4*)z_facial, emb, out);

    proj_kernel<<<BB, 256, SM_TOTAL_FLOATS * 4>>>(
        (const float4*)z_text, (const float4*)z_audio, (const float4*)z_facial,
        (const float4*)Wq, bq, (const float4*)Wk, bk, emb, out);
}

// round 3
// speedup vs baseline: 7.0051x; 7.0051x over previous
#include <cuda_runtime.h>
#include <cuda_bf16.h>
#include <cstdint>
#include <math.h>

// Problem constants
#define BB 8192
#define P3 24          // 3*N nodes per sample
#define E_PER 90
#define EDGE_DIM 16
#define NROWS 196608   // B * 24

// Output layout (float32 concat of the 4 reference outputs)
#define OFF_NODE 0
#define OFF_EI 50331648
#define EI_HALF 737280
#define OFF_EA 51806208
#define OFF_BV 63602688

// ---------------------------------------------------------------------------
// device scratch
// ---------------------------------------------------------------------------
__device__ __align__(16) __nv_bfloat16 g_Y[(size_t)NROWS * 256];   // [q(128)|k(128)]
__device__ __align__(16) __nv_bfloat16 g_Wb[256 * 256];            // Wcat bf16, [n][k]

__device__ __forceinline__ uint32_t smem_u32(const void* p) {
    uint32_t a;
    asm("{ .reg .u64 t; cvta.to.shared.u64 t, %1; cvt.u32.u64 %0, t; }"
        : "=r"(a) : "l"(p));
    return a;
}

#define LDSM_X4(r0, r1, r2, r3, addr) \
    asm volatile("ldmatrix.sync.aligned.m8n8.x4.shared.b16 {%0,%1,%2,%3}, [%4];" \
        : "=r"(r0), "=r"(r1), "=r"(r2), "=r"(r3) : "r"(addr))

__device__ __forceinline__ void mma16816(float* d, uint32_t a0, uint32_t a1,
                                         uint32_t a2, uint32_t a3,
                                         uint32_t b0, uint32_t b1) {
    asm volatile(
        "mma.sync.aligned.m16n8k16.row.col.f32.bf16.bf16.f32 "
        "{%0,%1,%2,%3}, {%4,%5,%6,%7}, {%8,%9}, {%0,%1,%2,%3};"
        : "+f"(d[0]), "+f"(d[1]), "+f"(d[2]), "+f"(d[3])
        : "r"(a0), "r"(a1), "r"(a2), "r"(a3), "r"(b0), "r"(b1));
}

// ---------------------------------------------------------------------------
// prep: W = [Wq; Wk] -> bf16, row-major [n][k]
// ---------------------------------------------------------------------------
__global__ void __launch_bounds__(256)
prep_kernel(const float4* __restrict__ Wq4, const float4* __restrict__ Wk4)
{
    int idx = blockIdx.x * 256 + threadIdx.x;     // 0..16383 float4
    int n = idx >> 6, c4 = idx & 63;
    float4 v = (n < 128) ? Wq4[(size_t)n * 64 + c4]
                         : Wk4[(size_t)(n - 128) * 64 + c4];
    __nv_bfloat162 h0 = __float22bfloat162_rn(make_float2(v.x, v.y));
    __nv_bfloat162 h1 = __float22bfloat162_rn(make_float2(v.z, v.w));
    uint2 u;
    u.x = *reinterpret_cast<uint32_t*>(&h0);
    u.y = *reinterpret_cast<uint32_t*>(&h1);
    ((uint2*)g_Wb)[idx] = u;
}

// ---------------------------------------------------------------------------
// gemm: Y[g,0:128]=x@Wq^T+bq, Y[g,128:256]=x@Wk^T+bk  (bias added in epilogue)
// Also streams node_feats to out (fused copy).
// M=128/block, N=256, K=256. 512 thr = 16 warps (4M x 4N), HMMA m16n8k16.
// smem: bias(1KB) | A 128x264bf16 (67584B, 528B stride) | B 256x264bf16 (135168B)
// ---------------------------------------------------------------------------
#define A_STRIDE 528
#define SM_BIAS_B 0
#define SM_A_B 1024
#define SM_B_B (1024 + 67584)
#define SM_GEMM_TOTAL (1024 + 67584 + 135168)   // 203776

__global__ void __launch_bounds__(512, 1)
gemm_kernel(const float4* __restrict__ text, const float4* __restrict__ audio,
            const float4* __restrict__ facial,
            const float* __restrict__ bq, const float* __restrict__ bk,
            float* __restrict__ out)
{
    extern __shared__ char smc[];
    float* bias_s = (float*)(smc + SM_BIAS_B);
    char* As = smc + SM_A_B;
    char* Bs = smc + SM_B_B;

    const int t = threadIdx.x;
    const int l = t & 31;
    const int w = t >> 5;
    const int m0 = blockIdx.x * 128;

    if (t < 256) bias_s[t] = (t < 128) ? bq[t] : bk[t - 128];

    // ---- A tile load + fused node_feats copy ----
    float4* out4 = (float4*)(out + OFF_NODE);
#pragma unroll
    for (int it = 0; it < 16; ++it) {
        int idx = it * 512 + t;              // 0..8191
        int r = idx >> 6, c4 = idx & 63;
        int g = m0 + r;
        int s = g / 24, node = g - s * 24;
        const float4* src = (node < 8) ? text : ((node < 16) ? audio : facial);
        float4 v = src[((size_t)s * 8 + (node & 7)) * 64 + c4];
        out4[(size_t)g * 64 + c4] = v;
        __nv_bfloat162 h0 = __float22bfloat162_rn(make_float2(v.x, v.y));
        __nv_bfloat162 h1 = __float22bfloat162_rn(make_float2(v.z, v.w));
        uint2 u;
        u.x = *reinterpret_cast<uint32_t*>(&h0);
        u.y = *reinterpret_cast<uint32_t*>(&h1);
        *reinterpret_cast<uint2*>(As + r * A_STRIDE + c4 * 8) = u;
    }

    // ---- B tile copy (bf16 from g_Wb) ----
    const uint2* Wb2 = (const uint2*)g_Wb;
#pragma unroll
    for (int it = 0; it < 32; ++it) {
        int idx = it * 512 + t;              // 0..16383
        int n = idx >> 6, c4 = idx & 63;
        *reinterpret_cast<uint2*>(Bs + n * A_STRIDE + c4 * 8) = Wb2[idx];
    }
    __syncthreads();

    // ---- HMMA mainloop ----
    const int wm = w >> 2;    // 0..3, M=32 each
    const int wn = w & 3;     // 0..3, N=64 each
    const int g_ = l >> 2;
    const int tig = l & 3;

    const uint32_t As_u = smem_u32(As);
    const uint32_t Bs_u = smem_u32(Bs);
    const uint32_t a_lane = As_u + (wm * 32 + (l & 15)) * A_STRIDE + (l >> 4) * 16;
    const int brow16 = (l & 7) | (((l >> 4) & 1) << 3);
    const uint32_t b_lane = Bs_u + (wn * 64 + brow16) * A_STRIDE + ((l >> 3) & 1) * 16;

    float acc[2][8][4];
#pragma unroll
    for (int mt = 0; mt < 2; ++mt)
#pragma unroll
        for (int nt = 0; nt < 8; ++nt)
#pragma unroll
            for (int j = 0; j < 4; ++j) acc[mt][nt][j] = 0.0f;

#pragma unroll
    for (int ks = 0; ks < 16; ++ks) {
        uint32_t a[2][4];
        LDSM_X4(a[0][0], a[0][1], a[0][2], a[0][3], a_lane + ks * 32);
        LDSM_X4(a[1][0], a[1][1], a[1][2], a[1][3],
                a_lane + 16 * A_STRIDE + ks * 32);
        uint32_t b[4][4];
#pragma unroll
        for (int p = 0; p < 4; ++p)
            LDSM_X4(b[p][0], b[p][1], b[p][2], b[p][3],
                    b_lane + p * 16 * A_STRIDE + ks * 32);
#pragma unroll
        for (int mt = 0; mt < 2; ++mt)
#pragma unroll
            for (int nt = 0; nt < 8; ++nt) {
                int p = nt >> 1, hi = (nt & 1) * 2;
                mma16816(acc[mt][nt], a[mt][0], a[mt][1], a[mt][2], a[mt][3],
                         b[p][hi], b[p][hi + 1]);
            }
    }

    // ---- epilogue: +bias, bf16 pack, write Y ----
#pragma unroll
    for (int mt = 0; mt < 2; ++mt) {
        int m = m0 + wm * 32 + mt * 16 + g_;
#pragma unroll
        for (int nt = 0; nt < 8; ++nt) {
            int n = wn * 64 + nt * 8 + 2 * tig;
            float b0 = bias_s[n], b1 = bias_s[n + 1];
            __nv_bfloat162 h0 = __float22bfloat162_rn(
                make_float2(acc[mt][nt][0] + b0, acc[mt][nt][1] + b1));
            __nv_bfloat162 h1 = __float22bfloat162_rn(
                make_float2(acc[mt][nt][2] + b0, acc[mt][nt][3] + b1));
            *reinterpret_cast<uint32_t*>(g_Y + (size_t)m * 256 + n) =
                *reinterpret_cast<uint32_t*>(&h0);
            *reinterpret_cast<uint32_t*>(g_Y + (size_t)(m + 8) * 256 + n) =
                *reinterpret_cast<uint32_t*>(&h1);
        }
    }
}

// ---------------------------------------------------------------------------
// epilogue: edge_index + temporal attrs + batch_vec + dots -> cross attrs
// ---------------------------------------------------------------------------
__global__ void __launch_bounds__(768)
epi_kernel(const float* __restrict__ emb, float* __restrict__ out)
{
    __shared__ float disc_s[24];
    const int b = blockIdx.x;
    const int t = threadIdx.x;
    const int l = t & 31;
    const int w = t >> 5;           // 0..23 = pair index

    // ---- edge_index ----
    if (t < E_PER) {
        int src, dst;
        if (t < 42) {
            int m = t / 14, r = t % 14, i = r >> 1, d = r & 1;
            int u_ = m * 8 + i, v_ = u_ + 1;
            src = d ? v_ : u_;
            dst = d ? u_ : v_;
        } else {
            int e2 = t - 42;
            int P = e2 >> 4, r = e2 & 15, i = r >> 1, d = r & 1;
            int oa = (P == 2) ? 8 : 0;
            int ob = (P == 0) ? 8 : 16;
            int a_ = oa + i, b_ = ob + i;
            src = d ? b_ : a_;
            dst = d ? a_ : b_;
        }
        out[OFF_EI + b * E_PER + t]           = (float)(src + b * P3);
        out[OFF_EI + EI_HALF + b * E_PER + t] = (float)(dst + b * P3);
    }

    // ---- temporal edge_attr (42 edges x 16) ----
    if (t < 672) {
        int e = t >> 4, j = t & 15;
        int m = e / 14;
        float v;
        if (j < 8)        v = emb[m * 8 + j];
        else if (j == 9)  v = 0.125f;
        else if (j == 10) v = 1.0f;
        else if (j == 11) v = m * 0.25f;
        else              v = 0.0f;
        out[OFF_EA + (size_t)(b * E_PER + e) * EDGE_DIM + j] = v;
    }

    // ---- batch_vec ----
    if (t >= 672 && t < 672 + P3)
        out[OFF_BV + b * P3 + (t - 672)] = (float)b;

    // ---- normalized dots ----
    {
        const int P = w >> 3, i = w & 7;
        const int qnode = (P < 2) ? i : (8 + i);
        const int knode = (P == 0) ? (8 + i) : (16 + i);
        const uint2* qrow = (const uint2*)(g_Y + ((size_t)b * 24 + qnode) * 256);
        const uint2* krow = (const uint2*)(g_Y + ((size_t)b * 24 + knode) * 256 + 128);
        uint2 qu = qrow[l];
        uint2 ku = krow[l];
        float2 q0 = __bfloat1622float2(*reinterpret_cast<__nv_bfloat162*>(&qu.x));
        float2 q1 = __bfloat1622float2(*reinterpret_cast<__nv_bfloat162*>(&qu.y));
        float2 k0 = __bfloat1622float2(*reinterpret_cast<__nv_bfloat162*>(&ku.x));
        float2 k1 = __bfloat1622float2(*reinterpret_cast<__nv_bfloat162*>(&ku.y));
        float sqk = q0.x * k0.x + q0.y * k0.y + q1.x * k1.x + q1.y * k1.y;
        float sqq = q0.x * q0.x + q0.y * q0.y + q1.x * q1.x + q1.y * q1.y;
        float skk = k0.x * k0.x + k0.y * k0.y + k1.x * k1.x + k1.y * k1.y;
#pragma unroll
        for (int off = 16; off > 0; off >>= 1) {
            sqk += __shfl_xor_sync(0xffffffffu, sqk, off);
            sqq += __shfl_xor_sync(0xffffffffu, sqq, off);
            skk += __shfl_xor_sync(0xffffffffu, skk, off);
        }
        if (l == 0) {
            float qn = fmaxf(sqrtf(sqq), 1e-12f);
            float kn = fmaxf(sqrtf(skk), 1e-12f);
            float dv = sqk / (qn * kn);
            disc_s[w] = 1.0f - 1.0f / (1.0f + expf(-dv));
        }
    }
    __syncthreads();

    // ---- cross edge attrs: 24 pairs * 2 dirs * 16 = 768 ----
    {
        const int p = t >> 5, r = t & 31;
        const int e = 42 + 2 * p + (r >> 4);
        const int j = r & 15;
        float disc = disc_s[p];
        int et = (disc > 0.4f) ? 4 : 3;
        float v;
        if (j < 8)        v = emb[et * 8 + j];
        else if (j == 8)  v = disc;
        else if (j == 11) v = et * 0.25f;
        else              v = 0.0f;
        out[OFF_EA + (size_t)(b * E_PER + e) * EDGE_DIM + j] = v;
    }
}

// ---------------------------------------------------------------------------
extern "C" void kernel_launch(void* const* d_in, const int* in_sizes, int n_in,
                              void* d_out, int out_size)
{
    const float* z_text   = (const float*)d_in[0];
    const float* z_audio  = (const float*)d_in[1];
    const float* z_facial = (const float*)d_in[2];
    const float* Wq       = (const float*)d_in[3];
    const float* bq       = (const float*)d_in[4];
    const float* Wk       = (const float*)d_in[5];
    const float* bk       = (const float*)d_in[6];
    const float* emb      = (const float*)d_in[7];
    float* out = (float*)d_out;

    cudaFuncSetAttribute(gemm_kernel, cudaFuncAttributeMaxDynamicSharedMemorySize,
                         SM_GEMM_TOTAL);

    prep_kernel<<<64, 256>>>((const float4*)Wq, (const float4*)Wk);

    gemm_kernel<<<NROWS / 128, 512, SM_GEMM_TOTAL>>>(
        (const float4*)z_text, (const float4*)z_audio, (const float4*)z_facial,
        bq, bk, out);

    epi_kernel<<<BB, 768>>>(emb, out);
}

// round 4
// speedup vs baseline: 7.7004x; 1.0993x over previous
#include <cuda_runtime.h>
#include <cuda_bf16.h>
#include <cstdint>
#include <math.h>

// Problem constants
#define BB 8192
#define P3 24
#define E_PER 90
#define EDGE_DIM 16
#define NROWS 196608   // B * 24

// Output layout (float32 concat of the 4 reference outputs)
#define OFF_NODE 0
#define OFF_EI 50331648
#define EI_HALF 737280
#define OFF_EA 51806208
#define OFF_BV 63602688

// ---------------------------------------------------------------------------
__device__ __align__(16) __nv_bfloat16 g_Wb[256 * 256];   // Wcat bf16, [n][k]

__device__ __forceinline__ uint32_t smem_u32(const void* p) {
    uint32_t a;
    asm("{ .reg .u64 t; cvta.to.shared.u64 t, %1; cvt.u32.u64 %0, t; }"
        : "=r"(a) : "l"(p));
    return a;
}

#define LDSM_X4(r0, r1, r2, r3, addr) \
    asm volatile("ldmatrix.sync.aligned.m8n8.x4.shared.b16 {%0,%1,%2,%3}, [%4];" \
        : "=r"(r0), "=r"(r1), "=r"(r2), "=r"(r3) : "r"(addr))

__device__ __forceinline__ void mma16816(float* d, uint32_t a0, uint32_t a1,
                                         uint32_t a2, uint32_t a3,
                                         uint32_t b0, uint32_t b1) {
    asm volatile(
        "mma.sync.aligned.m16n8k16.row.col.f32.bf16.bf16.f32 "
        "{%0,%1,%2,%3}, {%4,%5,%6,%7}, {%8,%9}, {%0,%1,%2,%3};"
        : "+f"(d[0]), "+f"(d[1]), "+f"(d[2]), "+f"(d[3])
        : "r"(a0), "r"(a1), "r"(a2), "r"(a3), "r"(b0), "r"(b1));
}

// ---------------------------------------------------------------------------
// prep: W = [Wq; Wk] -> bf16, row-major [n][k]
// ---------------------------------------------------------------------------
__global__ void __launch_bounds__(256)
prep_kernel(const float4* __restrict__ Wq4, const float4* __restrict__ Wk4)
{
    int idx = blockIdx.x * 256 + threadIdx.x;     // 0..16383 float4
    int n = idx >> 6, c4 = idx & 63;
    float4 v = (n < 128) ? Wq4[(size_t)n * 64 + c4]
                         : Wk4[(size_t)(n - 128) * 64 + c4];
    __nv_bfloat162 h0 = __float22bfloat162_rn(make_float2(v.x, v.y));
    __nv_bfloat162 h1 = __float22bfloat162_rn(make_float2(v.z, v.w));
    uint2 u;
    u.x = *reinterpret_cast<uint32_t*>(&h0);
    u.y = *reinterpret_cast<uint32_t*>(&h1);
    ((uint2*)g_Wb)[idx] = u;
}

// ---------------------------------------------------------------------------
// fused kernel: 8 samples (192 rows) per block.
//  - A tile load fused with node_feats copy
//  - 2 N-passes of 128 cols (q, k) of HMMA GEMM; Yq/Yk parked in smem over
//    the dead half of the B tile
//  - in-smem normalized dots -> disc -> all edge attrs / index / batch_vec
// smem: bias(1024) | disc(768) | pad | A 192x512B swz | B 256x512B swz
// ---------------------------------------------------------------------------
#define FS_BIAS 0
#define FS_DISC 1024
#define FS_A    2048
#define FS_B    100352          // 2048 + 192*512
#define FS_YQ   100352          // over B rows 0..127 (dead after pass 0)
#define FS_YK   165888          // over B rows 128..255 (dead after pass 1)
#define FS_TOTAL 231424         // 100352 + 256*512

__global__ void __launch_bounds__(512, 1)
fused_kernel(const float4* __restrict__ text, const float4* __restrict__ audio,
             const float4* __restrict__ facial,
             const float* __restrict__ bq, const float* __restrict__ bk,
             const float* __restrict__ emb, float* __restrict__ out)
{
    extern __shared__ char smc[];
    float* bias_s = (float*)(smc + FS_BIAS);
    float* disc_s = (float*)(smc + FS_DISC);   // 192 floats

    const int t = threadIdx.x;
    const int l = t & 31;
    const int w = t >> 5;              // 0..15
    const int s0 = blockIdx.x * 8;     // first sample
    const int m0 = blockIdx.x * 192;   // first global row

    if (t < 256) bias_s[t] = (t < 128) ? bq[t] : bk[t - 128];

    // ---- A tile load (bf16, swizzled) + fused node_feats copy ----
    float4* out4 = (float4*)(out + OFF_NODE);
#pragma unroll
    for (int it = 0; it < 24; ++it) {
        int idx = it * 512 + t;              // 0..12287
        int r = idx >> 6, c4 = idx & 63;
        int sl = r / 24, node = r - sl * 24;
        const float4* src = (node < 8) ? text : ((node < 16) ? audio : facial);
        float4 v = src[((size_t)(s0 + sl) * 8 + (node & 7)) * 64 + c4];
        out4[(size_t)(m0 + r) * 64 + c4] = v;
        __nv_bfloat162 h0 = __float22bfloat162_rn(make_float2(v.x, v.y));
        __nv_bfloat162 h1 = __float22bfloat162_rn(make_float2(v.z, v.w));
        uint2 u;
        u.x = *reinterpret_cast<uint32_t*>(&h0);
        u.y = *reinterpret_cast<uint32_t*>(&h1);
        int off = (r * 512 + c4 * 8) ^ ((r & 7) << 4);
        *reinterpret_cast<uint2*>(smc + FS_A + off) = u;
    }

    // ---- B tile copy (bf16 from g_Wb, swizzled) ----
    const uint2* Wb2 = (const uint2*)g_Wb;
#pragma unroll
    for (int it = 0; it < 32; ++it) {
        int idx = it * 512 + t;              // 0..16383
        int n = idx >> 6, c4 = idx & 63;
        int off = (n * 512 + c4 * 8) ^ ((n & 7) << 4);
        *reinterpret_cast<uint2*>(smc + FS_B + off) = Wb2[idx];
    }
    __syncthreads();

    // ---- HMMA: 16 warps = 4M (48 rows) x 4N (32 cols per pass) ----
    const int wm = w >> 2;
    const int wn = w & 3;
    const int g_ = l >> 2;
    const int tig = l & 3;
    const int SX = (l & 7) << 4;       // swizzle xor for ldmatrix lanes

    const uint32_t As_u = smem_u32(smc + FS_A);
    const uint32_t Bs_u = smem_u32(smc + FS_B);

    int a_pre[3];
#pragma unroll
    for (int mt = 0; mt < 3; ++mt) {
        int row = wm * 48 + mt * 16 + (l & 15);
        a_pre[mt] = row * 512 + (l >> 4) * 16;
    }
    const int brow16 = (l & 7) | (((l >> 4) & 1) << 3);

#pragma unroll
    for (int pass = 0; pass < 2; ++pass) {
        int b_pre[2];
#pragma unroll
        for (int p = 0; p < 2; ++p) {
            int n = pass * 128 + wn * 32 + p * 16 + brow16;
            b_pre[p] = n * 512 + ((l >> 3) & 1) * 16;
        }

        float acc[3][4][4];
#pragma unroll
        for (int mt = 0; mt < 3; ++mt)
#pragma unroll
            for (int nt = 0; nt < 4; ++nt)
#pragma unroll
                for (int j = 0; j < 4; ++j) acc[mt][nt][j] = 0.0f;

#pragma unroll
        for (int ks = 0; ks < 16; ++ks) {
            uint32_t a[3][4];
#pragma unroll
            for (int mt = 0; mt < 3; ++mt)
                LDSM_X4(a[mt][0], a[mt][1], a[mt][2], a[mt][3],
                        As_u + ((a_pre[mt] + ks * 32) ^ SX));
            uint32_t b[2][4];
#pragma unroll
            for (int p = 0; p < 2; ++p)
                LDSM_X4(b[p][0], b[p][1], b[p][2], b[p][3],
                        Bs_u + ((b_pre[p] + ks * 32) ^ SX));
#pragma unroll
            for (int mt = 0; mt < 3; ++mt)
#pragma unroll
                for (int nt = 0; nt < 4; ++nt) {
                    int p = nt >> 1, hi = (nt & 1) * 2;
                    mma16816(acc[mt][nt], a[mt][0], a[mt][1], a[mt][2], a[mt][3],
                             b[p][hi], b[p][hi + 1]);
                }
        }

        // all warps done reading B half 'pass' before overwriting it with Y
        __syncthreads();

        char* Ybuf = smc + (pass ? FS_YK : FS_YQ);
        const int SY = g_ << 4;
#pragma unroll
        for (int mt = 0; mt < 3; ++mt) {
            int mrow = wm * 48 + mt * 16 + g_;
#pragma unroll
            for (int nt = 0; nt < 4; ++nt) {
                int n = wn * 32 + nt * 8 + tig * 2;
                float b0 = bias_s[pass * 128 + n];
                float b1 = bias_s[pass * 128 + n + 1];
                __nv_bfloat162 h0 = __float22bfloat162_rn(
                    make_float2(acc[mt][nt][0] + b0, acc[mt][nt][1] + b1));
                __nv_bfloat162 h1 = __float22bfloat162_rn(
                    make_float2(acc[mt][nt][2] + b0, acc[mt][nt][3] + b1));
                *reinterpret_cast<uint32_t*>(
                    Ybuf + ((mrow * 256 + n * 2) ^ SY)) =
                    *reinterpret_cast<uint32_t*>(&h0);
                *reinterpret_cast<uint32_t*>(
                    Ybuf + (((mrow + 8) * 256 + n * 2) ^ SY)) =
                    *reinterpret_cast<uint32_t*>(&h1);
            }
        }
    }
    __syncthreads();

    // ---- dots: 192 pair-dots, 12 per warp ----
#pragma unroll
    for (int j = 0; j < 12; ++j) {
        int d = w * 12 + j;
        int sl = d / 24, p = d - sl * 24;
        int P = p >> 3, i = p & 7;
        int qrow = sl * 24 + ((P < 2) ? i : (8 + i));
        int krow = sl * 24 + ((P == 0) ? (8 + i) : (16 + i));
        uint2 qu = *reinterpret_cast<const uint2*>(
            smc + FS_YQ + ((qrow * 256 + l * 8) ^ ((qrow & 7) << 4)));
        uint2 ku = *reinterpret_cast<const uint2*>(
            smc + FS_YK + ((krow * 256 + l * 8) ^ ((krow & 7) << 4)));
        float2 q0 = __bfloat1622float2(*reinterpret_cast<__nv_bfloat162*>(&qu.x));
        float2 q1 = __bfloat1622float2(*reinterpret_cast<__nv_bfloat162*>(&qu.y));
        float2 k0 = __bfloat1622float2(*reinterpret_cast<__nv_bfloat162*>(&ku.x));
        float2 k1 = __bfloat1622float2(*reinterpret_cast<__nv_bfloat162*>(&ku.y));
        float sqk = q0.x * k0.x + q0.y * k0.y + q1.x * k1.x + q1.y * k1.y;
        float sqq = q0.x * q0.x + q0.y * q0.y + q1.x * q1.x + q1.y * q1.y;
        float skk = k0.x * k0.x + k0.y * k0.y + k1.x * k1.x + k1.y * k1.y;
#pragma unroll
        for (int off = 16; off > 0; off >>= 1) {
            sqk += __shfl_xor_sync(0xffffffffu, sqk, off);
            sqq += __shfl_xor_sync(0xffffffffu, sqq, off);
            skk += __shfl_xor_sync(0xffffffffu, skk, off);
        }
        if (l == 0) {
            float qn = fmaxf(sqrtf(sqq), 1e-12f);
            float kn = fmaxf(sqrtf(skk), 1e-12f);
            float dv = sqk / (qn * kn);
            disc_s[d] = 1.0f - 1.0f / (1.0f + expf(-dv));
        }
    }
    __syncthreads();

    // ---- cross edge attrs: 8 samples * 48 edges * 16 = 6144 ----
#pragma unroll
    for (int it = 0; it < 12; ++it) {
        int o = it * 512 + t;
        int sl = o / 768, rem = o - sl * 768;
        int p = rem >> 5, r = rem & 31;
        int e = 42 + 2 * p + (r >> 4);
        int jj = r & 15;
        float disc = disc_s[sl * 24 + p];
        int et = (disc > 0.4f) ? 4 : 3;
        float v;
        if (jj < 8)        v = emb[et * 8 + jj];
        else if (jj == 8)  v = disc;
        else if (jj == 11) v = et * 0.25f;
        else               v = 0.0f;
        out[OFF_EA + (size_t)((s0 + sl) * E_PER + e) * EDGE_DIM + jj] = v;
    }

    // ---- temporal edge attrs: 8 * 42 * 16 = 5376 ----
    for (int o = t; o < 5376; o += 512) {
        int sl = o / 672, rem = o - sl * 672;
        int e = rem >> 4, jj = rem & 15;
        int m = e / 14;
        float v;
        if (jj < 8)        v = emb[m * 8 + jj];
        else if (jj == 9)  v = 0.125f;
        else if (jj == 10) v = 1.0f;
        else if (jj == 11) v = m * 0.25f;
        else               v = 0.0f;
        out[OFF_EA + (size_t)((s0 + sl) * E_PER + e) * EDGE_DIM + jj] = v;
    }

    // ---- edge_index: 8 * 90 ----
    for (int o = t; o < 720; o += 512) {
        int sl = o / 90, e = o - sl * 90;
        int src, dst;
        if (e < 42) {
            int m = e / 14, r = e % 14, i = r >> 1, d = r & 1;
            int u_ = m * 8 + i, v_ = u_ + 1;
            src = d ? v_ : u_;
            dst = d ? u_ : v_;
        } else {
            int e2 = e - 42;
            int P = e2 >> 4, r = e2 & 15, i = r >> 1, d = r & 1;
            int oa = (P == 2) ? 8 : 0;
            int ob = (P == 0) ? 8 : 16;
            int a_ = oa + i, b_ = ob + i;
            src = d ? b_ : a_;
            dst = d ? a_ : b_;
        }
        int b = s0 + sl;
        out[OFF_EI + b * E_PER + e]           = (float)(src + b * P3);
        out[OFF_EI + EI_HALF + b * E_PER + e] = (float)(dst + b * P3);
    }

    // ---- batch_vec: 192 ----
    if (t < 192) out[OFF_BV + m0 + t] = (float)(s0 + t / 24);
}

// ---------------------------------------------------------------------------
extern "C" void kernel_launch(void* const* d_in, const int* in_sizes, int n_in,
                              void* d_out, int out_size)
{
    const float* z_text   = (const float*)d_in[0];
    const float* z_audio  = (const float*)d_in[1];
    const float* z_facial = (const float*)d_in[2];
    const float* Wq       = (const float*)d_in[3];
    const float* bq       = (const float*)d_in[4];
    const float* Wk       = (const float*)d_in[5];
    const float* bk       = (const float*)d_in[6];
    const float* emb      = (const float*)d_in[7];
    float* out = (float*)d_out;

    cudaFuncSetAttribute(fused_kernel, cudaFuncAttributeMaxDynamicSharedMemorySize,
                         FS_TOTAL);

    prep_kernel<<<64, 256>>>((const float4*)Wq, (const float4*)Wk);

    fused_kernel<<<NROWS / 192, 512, FS_TOTAL>>>(
        (const float4*)z_text, (const float4*)z_audio, (const float4*)z_facial,
        bq, bk, emb, out);
}